// round 13
// baseline (speedup 1.0000x reference)
#include <cuda_runtime.h>

// ---------------------------------------------------------------------------
// QuantumDMRGLayer MPS chain contraction, v6.
// 8 lanes per chain, lane j holds the pair (v[2j], v[2j+1]) in TWO REGISTERS.
// Per step: 16 shfl.sync gather all v entries (group-local), dup to f32x2,
// 32 fma2 against the repacked A (register double-buffered LDG), packed
// result IS the next v pair. NO shared memory / syncwarp in the loop.
// ---------------------------------------------------------------------------

typedef unsigned long long ull;

#define MDIM 16

// Repacked A: float4 g_A2[dir][site][c=0..15][j=0..7]
//  c in [0,8):  A0, summation pair i0=2c,i0+1 ; c in [8,16): A1
//  dir0 (v@M):  {A[i0][2j], A[i0][2j+1], A[i0+1][2j], A[i0+1][2j+1]}
//  dir1 (M@v):  {A[2j][n0], A[2j+1][n0], A[2j][n0+1], A[2j+1][n0+1]}
__device__ float4 g_A2[2 * 200 * 128];               // 800 KB max
__device__ float  g_vout[2][4096 * MDIM];

// ---------------------------- f32x2 helpers --------------------------------
__device__ __forceinline__ ull mul2(ull a, ull b) {
    ull d; asm("mul.rn.f32x2 %0, %1, %2;" : "=l"(d) : "l"(a), "l"(b)); return d;
}
__device__ __forceinline__ ull fma2(ull a, ull b, ull c) {
    ull d; asm("fma.rn.f32x2 %0, %1, %2, %3;" : "=l"(d) : "l"(a), "l"(b), "l"(c)); return d;
}
__device__ __forceinline__ ull add2(ull a, ull b) {
    ull d; asm("add.rn.f32x2 %0, %1, %2;" : "=l"(d) : "l"(a), "l"(b)); return d;
}
__device__ __forceinline__ ull dup2(float f) {
    ull d; asm("mov.b64 %0, {%1, %1};" : "=l"(d) : "f"(f)); return d;
}
__device__ __forceinline__ void unpack2(ull v, float& lo, float& hi) {
    asm("mov.b64 {%0, %1}, %2;" : "=f"(lo), "=f"(hi) : "l"(v));
}

// ---------------------------- prep: repack A -------------------------------
__global__ void prep_kernel(const float* __restrict__ A_mid, int nmat) {
    __shared__ float sA[1024];
    int s0 = blockIdx.x * 2, tid = threadIdx.x;
    int nsite = (s0 + 1 < nmat) ? 2 : 1;
    if (tid < nsite * 128)
        reinterpret_cast<float4*>(sA)[tid] =
            reinterpret_cast<const float4*>(A_mid + (size_t)s0 * 512)[tid];
    __syncthreads();
    #pragma unroll
    for (int k = 0; k < 2; k++) {
        int o = tid * 2 + k;                 // [0, 512)
        int sl  = o >> 8;                    // local site 0/1
        if (sl >= nsite) continue;
        int rem = o & 255;
        int dir = rem >> 7, c = (rem >> 3) & 15, j = rem & 7;
        const float* Bm = sA + sl * 512 + ((c >= 8) ? 256 : 0);
        int cc = c & 7;
        float4 v;
        if (dir == 0) {
            int i0 = 2 * cc;
            v = make_float4(Bm[i0 * 16 + 2 * j],       Bm[i0 * 16 + 2 * j + 1],
                            Bm[(i0 + 1) * 16 + 2 * j], Bm[(i0 + 1) * 16 + 2 * j + 1]);
        } else {
            int n0 = 2 * cc;
            v = make_float4(Bm[2 * j * 16 + n0],     Bm[(2 * j + 1) * 16 + n0],
                            Bm[2 * j * 16 + n0 + 1], Bm[(2 * j + 1) * 16 + n0 + 1]);
        }
        int s = s0 + sl;
        g_A2[((size_t)(dir * nmat + s) * 16 + c) * 8 + j] = v;
    }
}

__device__ __forceinline__ void loadA(ulonglong2 (&R)[16], const ulonglong2* p) {
    #pragma unroll
    for (int c = 0; c < 16; c++) R[c] = p[c * 8];   // 128B stride, 1 line each
}

// ------------------------- one chain micro-step ----------------------------
// r0/r1: this lane's pair. sbase = lane & 24 (group base for shfl).
__device__ __forceinline__ void mps_step(const ulonglong2 (&A)[16],
                                         int sbase, float2 xx,
                                         float& r0, float& r1) {
    ull e0, e1, f0, f1;
    {
        float lo = __shfl_sync(0xffffffffu, r0, sbase | 0);
        float hi = __shfl_sync(0xffffffffu, r1, sbase | 0);
        ull dlo = dup2(lo), dhi = dup2(hi);
        e0 = mul2(dlo, A[0].x);  e1 = mul2(dhi, A[0].y);
        f0 = mul2(dlo, A[8].x);  f1 = mul2(dhi, A[8].y);
    }
    #pragma unroll
    for (int c = 1; c < 8; c++) {
        float lo = __shfl_sync(0xffffffffu, r0, sbase | c);
        float hi = __shfl_sync(0xffffffffu, r1, sbase | c);
        ull dlo = dup2(lo), dhi = dup2(hi);
        e0 = fma2(dlo, A[c].x, e0);      e1 = fma2(dhi, A[c].y, e1);
        f0 = fma2(dlo, A[c + 8].x, f0);  f1 = fma2(dhi, A[c + 8].y, f1);
    }
    ull s0 = add2(e0, e1), s1 = add2(f0, f1);
    ull res = fma2(dup2(xx.y), s1, mul2(dup2(xx.x), s0));
    unpack2(res, r0, r1);
}

// ----------------------------- main chain kernel ---------------------------
// grid (ceil(B/16), 2), block 128: 16 chains/CTA, 8 lanes each, 4 chains/warp.
__global__ void __launch_bounds__(128, 2)
chain_kernel(const float* __restrict__ inputs,
             const float* __restrict__ A_left,
             const float* __restrict__ A_right,
             const int* __restrict__ pos_ptr,
             int B, int L) {
    const int nmat = L - 2;
    const int dir  = blockIdx.y;
    const int b0   = blockIdx.x * 16;
    const int XL   = 2 * L;

    __shared__ float sh_x[16 * 400];

    const int tid   = threadIdx.x;
    const int j     = tid & 7;
    const int grp   = tid >> 3;          // 0..15 = sample index in CTA
    const int sbase = tid & 24;          // group base within warp

    // stage inputs (one-time CTA barrier)
    {
        int avail = B - b0; if (avail > 16) avail = 16;
        const float4* src = reinterpret_cast<const float4*>(inputs + (size_t)b0 * XL);
        float4* dst = reinterpret_cast<float4*>(sh_x);
        int n4 = avail * (XL / 4);
        for (int i = tid; i < n4; i += 128) dst[i] = src[i];
    }

    int pos = pos_ptr ? *pos_ptr : 98;
    if (pos < 0) pos = 0;
    if (pos > nmat) pos = nmat;
    const int nsteps = (dir == 0) ? pos : (nmat - pos);

    // A walk
    const ulonglong2* Abase =
        reinterpret_cast<const ulonglong2*>(g_A2) + (size_t)dir * nmat * 128 + j;
    const ptrdiff_t mstep = dir ? -128 : 128;
    const int m0 = dir ? (nmat - 1) : 0;
    const ulonglong2* pA = Abase + (ptrdiff_t)m0 * 128;

    ulonglong2 Ar[16], Br[16];
    if (nsteps > 0) loadA(Ar, pA);
    const ulonglong2* pAn = pA + mstep;

    __syncthreads();   // x staged

    const float* xrow = sh_x + grp * XL;

    // boundary vector init -> registers
    float r0, r1;
    {
        const float* Ab = (dir == 0) ? A_left : A_right;
        const int xsit = (dir == 0) ? 0 : (L - 1);
        float x0 = xrow[xsit * 2], x1 = xrow[xsit * 2 + 1];
        r0 = fmaf(x1, Ab[MDIM + 2 * j],     x0 * Ab[2 * j]);
        r1 = fmaf(x1, Ab[MDIM + 2 * j + 1], x0 * Ab[2 * j + 1]);
    }

    // x walk: dir0 sites 1..pos ascending, dir1 sites nmat..pos+1 descending
    const float* xs = xrow + (dir ? nmat * 2 : 2);
    const ptrdiff_t xstep = dir ? -2 : 2;

    int i = 0;
    while (i < nsteps) {
        {   // consume Ar, prefetch Br
            if (i + 1 < nsteps) { loadA(Br, pAn); pAn += mstep; }
            float2 xx = *reinterpret_cast<const float2*>(xs); xs += xstep;
            mps_step(Ar, sbase, xx, r0, r1);
            i++;
        }
        if (i >= nsteps) break;
        {   // consume Br, prefetch Ar
            if (i + 1 < nsteps) { loadA(Ar, pAn); pAn += mstep; }
            float2 xx = *reinterpret_cast<const float2*>(xs); xs += xstep;
            mps_step(Br, sbase, xx, r0, r1);
            i++;
        }
    }

    // write result pair
    {
        int b = b0 + grp;
        if (b < B)
            reinterpret_cast<float2*>(g_vout[dir] + (size_t)b * MDIM)[j] = make_float2(r0, r1);
    }
}

// ----------------------------- final contraction ---------------------------
__global__ void finish_kernel(const float* __restrict__ T_out,
                              float* __restrict__ out, int B, int NBL) {
    __shared__ float sh_T[MDIM * MDIM * 16];
    __shared__ float sh_l[16][MDIM + 1], sh_r[16][MDIM + 1];
    int b0 = blockIdx.x * 16;
    int tid = threadIdx.x, nt = blockDim.x;
    for (int i = tid; i < MDIM * MDIM * NBL; i += nt) sh_T[i] = T_out[i];
    for (int i = tid; i < 16 * MDIM; i += nt) {
        int s = i >> 4, m = i & 15;
        int b = b0 + s;
        float lv = 0.f, rv = 0.f;
        if (b < B) { lv = g_vout[0][b * MDIM + m]; rv = g_vout[1][b * MDIM + m]; }
        sh_l[s][m] = lv; sh_r[s][m] = rv;
    }
    __syncthreads();
    if (tid < 16 * NBL) {
        int s = tid / NBL, l = tid % NBL;
        int b = b0 + s;
        float acc = 0.f;
        #pragma unroll
        for (int m = 0; m < MDIM; m++) {
            float part = 0.f;
            #pragma unroll
            for (int n = 0; n < MDIM; n++)
                part = fmaf(sh_r[s][n], sh_T[(m * MDIM + n) * NBL + l], part);
            acc = fmaf(sh_l[s][m], part, acc);
        }
        if (b < B) out[b * NBL + l] = acc;
    }
}

// ------------------------------- launch ------------------------------------
extern "C" void kernel_launch(void* const* d_in, const int* in_sizes, int n_in,
                              void* d_out, int out_size) {
    const float* inputs  = (const float*)d_in[0];
    const float* A_left  = (const float*)d_in[1];
    const float* A_mid   = (const float*)d_in[2];
    const float* A_right = (const float*)d_in[3];
    const float* T_out   = (const float*)d_in[4];
    const int*   pos_ptr = (n_in >= 6) ? (const int*)d_in[5] : nullptr;

    int M    = in_sizes[1] / 2;                 // 16
    int nmat = in_sizes[2] / (2 * M * M);       // L - 2
    int L    = nmat + 2;
    int B    = in_sizes[0] / (2 * L);
    int NBL  = in_sizes[4] / (M * M);
    (void)out_size;

    prep_kernel<<<(nmat + 1) / 2, 256>>>(A_mid, nmat);

    dim3 grid((B + 15) / 16, 2);
    chain_kernel<<<grid, 128>>>(inputs, A_left, A_right, pos_ptr, B, L);

    finish_kernel<<<(B + 15) / 16, 256>>>(T_out, (float*)d_out, B, NBL);
}